// round 1
// baseline (speedup 1.0000x reference)
#include <cuda_runtime.h>
#include <cuda_bf16.h>
#include <cstdint>

#define D_DIM 4096
#define ROT_N 256

// Scratch (device globals — no allocation allowed in kernel_launch)
__device__ __align__(16) int8_t g_qx[(size_t)D_DIM * D_DIM];   // quantized activations [N, D]
__device__ __align__(16) int8_t g_wq[(size_t)D_DIM * D_DIM];   // int8 weights [D_out, D]
__device__ float g_sx[D_DIM];                                  // per-row activation scales

// ---------------------------------------------------------------------------
// Kernel 1: weight int32 -> int8 repack (values are in [-7,7])
// ---------------------------------------------------------------------------
__global__ void convert_w_kernel(const int* __restrict__ w, int total4) {
    int i = blockIdx.x * blockDim.x + threadIdx.x;
    if (i < total4) {
        int4 v = ((const int4*)w)[i];
        uint32_t p = (uint32_t)(v.x & 0xff)
                   | ((uint32_t)(v.y & 0xff) << 8)
                   | ((uint32_t)(v.z & 0xff) << 16)
                   | ((uint32_t)(v.w & 0xff) << 24);
        ((uint32_t*)g_wq)[i] = p;
    }
}

// ---------------------------------------------------------------------------
// Kernel 2: blockwise Hadamard (FWHT, 256-block) + per-row int4 quantization
// One CTA (256 threads) per row of x.
// Reference: x_rot = (x.reshape(-1,16,256) @ H)/..., H = Sylvester/sqrt(256)
//   -> FWHT then multiply by 1/16. scales = max|x_rot|/7; q = clip(round(x_rot/scales),-8,7)
// Note: the 1/16 cancels exactly (power of 2) in the ratio raw/(amax/7*16)*16.
// ---------------------------------------------------------------------------
__global__ __launch_bounds__(256) void had_quant_kernel(const float* __restrict__ x) {
    __shared__ float s[D_DIM];
    __shared__ float red[8];
    const int row = blockIdx.x;
    const int tid = threadIdx.x;

    // load row (vectorized)
    const float4* xr = (const float4*)(x + (size_t)row * D_DIM);
    float4* s4 = (float4*)s;
    #pragma unroll
    for (int i = tid; i < D_DIM / 4; i += 256) s4[i] = xr[i];
    __syncthreads();

    // FWHT within each 256-element block (pairs never cross block boundary for h<256)
    for (int h = 1; h < ROT_N; h <<= 1) {
        for (int p = tid; p < D_DIM / 2; p += 256) {
            int i = ((p / h) * (h << 1)) + (p & (h - 1));
            int j = i + h;
            float a = s[i], b = s[j];
            s[i] = a + b;
            s[j] = a - b;
        }
        __syncthreads();
    }

    // absmax of raw FWHT output (scaling by 1/16 is exact, applied below)
    float m = 0.f;
    for (int i = tid; i < D_DIM; i += 256) m = fmaxf(m, fabsf(s[i]));
    #pragma unroll
    for (int o = 16; o; o >>= 1) m = fmaxf(m, __shfl_xor_sync(0xffffffffu, m, o));
    if ((tid & 31) == 0) red[tid >> 5] = m;
    __syncthreads();
    if (tid < 8) {
        m = red[tid];
        #pragma unroll
        for (int o = 4; o; o >>= 1) m = fmaxf(m, __shfl_xor_sync(0xffu, m, o));
        if (tid == 0) red[0] = m;
    }
    __syncthreads();
    const float amax = red[0];
    const float scale = (amax * 0.0625f) / 7.0f;   // max|x_rot| / 7
    if (tid == 0) g_sx[row] = scale;

    // quantize: q = rint(x_rot / scale), correctly-rounded divide + round-half-even
    uint32_t* q4 = (uint32_t*)(g_qx + (size_t)row * D_DIM);
    for (int i = tid; i < D_DIM / 4; i += 256) {
        uint32_t packed = 0;
        #pragma unroll
        for (int b = 0; b < 4; b++) {
            float v = s[i * 4 + b] * 0.0625f;          // x_rot (exact pow2 scale)
            float qf = rintf(__fdiv_rn(v, scale));
            int qi = (int)qf;
            qi = max(-8, min(7, qi));
            packed |= ((uint32_t)(qi & 0xff)) << (8 * b);
        }
        q4[i] = packed;
    }
}

// ---------------------------------------------------------------------------
// Kernel 3: int8 GEMM  C[n,o] = sum_d qx[n,d]*wq[o,d]  via mma.sync m16n8k32.s8
// Tile 128x128x64, 8 warps (2x4), 64x32 per warp. Fused dequant epilogue.
// ---------------------------------------------------------------------------
#define BM 128
#define BN 128
#define BK 64
#define LDS_STRIDE 80   // 64 + 16 pad: 16B-aligned stores, conflict-free frag reads

__global__ __launch_bounds__(256, 2)
void gemm_s8_kernel(const float* __restrict__ sx_dummy,
                    const float* __restrict__ ws,
                    const float* __restrict__ bias,
                    float* __restrict__ out) {
    __shared__ int8_t sA[BM * LDS_STRIDE];
    __shared__ int8_t sB[BN * LDS_STRIDE];

    const int tid  = threadIdx.x;
    const int warp = tid >> 5;
    const int lane = tid & 31;
    const int g    = lane >> 2;    // group id (row within fragment)
    const int tg   = lane & 3;     // thread-in-group
    const int wm   = warp & 1;     // 2 warps over M (64 rows each)
    const int wn   = warp >> 1;    // 4 warps over N (32 cols each)
    const int bm0  = blockIdx.y * BM;
    const int bn0  = blockIdx.x * BN;

    int acc[4][4][4];
    #pragma unroll
    for (int mi = 0; mi < 4; mi++)
        #pragma unroll
        for (int ni = 0; ni < 4; ni++)
            #pragma unroll
            for (int r = 0; r < 4; r++) acc[mi][ni][r] = 0;

    const int8_t* A = g_qx;
    const int8_t* B = g_wq;

    for (int kt = 0; kt < D_DIM / BK; ++kt) {
        // cooperative tile load: 512 x 16B per tile, 256 threads x 2
        #pragma unroll
        for (int i = 0; i < 2; i++) {
            int idx = tid + i * 256;          // 0..511
            int r   = idx >> 2;               // 0..127
            int c   = (idx & 3) << 4;         // 0,16,32,48
            *(int4*)&sA[r * LDS_STRIDE + c] =
                *(const int4*)&A[(size_t)(bm0 + r) * D_DIM + kt * BK + c];
            *(int4*)&sB[r * LDS_STRIDE + c] =
                *(const int4*)&B[(size_t)(bn0 + r) * D_DIM + kt * BK + c];
        }
        __syncthreads();

        #pragma unroll
        for (int kk = 0; kk < 2; ++kk) {
            const int ka = kk * 32 + tg * 4;
            uint32_t a[4][4], b[4][2];
            #pragma unroll
            for (int mi = 0; mi < 4; mi++) {
                int r = wm * 64 + mi * 16 + g;
                a[mi][0] = *(const uint32_t*)&sA[r * LDS_STRIDE + ka];
                a[mi][1] = *(const uint32_t*)&sA[(r + 8) * LDS_STRIDE + ka];
                a[mi][2] = *(const uint32_t*)&sA[r * LDS_STRIDE + ka + 16];
                a[mi][3] = *(const uint32_t*)&sA[(r + 8) * LDS_STRIDE + ka + 16];
            }
            #pragma unroll
            for (int ni = 0; ni < 4; ni++) {
                int n = wn * 32 + ni * 8 + g;
                b[ni][0] = *(const uint32_t*)&sB[n * LDS_STRIDE + ka];
                b[ni][1] = *(const uint32_t*)&sB[n * LDS_STRIDE + ka + 16];
            }
            #pragma unroll
            for (int mi = 0; mi < 4; mi++)
                #pragma unroll
                for (int ni = 0; ni < 4; ni++)
                    asm volatile(
                        "mma.sync.aligned.m16n8k32.row.col.s32.s8.s8.s32 "
                        "{%0,%1,%2,%3}, {%4,%5,%6,%7}, {%8,%9}, {%0,%1,%2,%3};\n"
                        : "+r"(acc[mi][ni][0]), "+r"(acc[mi][ni][1]),
                          "+r"(acc[mi][ni][2]), "+r"(acc[mi][ni][3])
                        : "r"(a[mi][0]), "r"(a[mi][1]), "r"(a[mi][2]), "r"(a[mi][3]),
                          "r"(b[ni][0]), "r"(b[ni][1]));
        }
        __syncthreads();
    }

    // epilogue: out = acc * sx[row] * ws[col] + bias[col]
    (void)sx_dummy;
    #pragma unroll
    for (int mi = 0; mi < 4; mi++) {
        int r0 = bm0 + wm * 64 + mi * 16 + g;
        float s0 = g_sx[r0];
        float s1 = g_sx[r0 + 8];
        #pragma unroll
        for (int ni = 0; ni < 4; ni++) {
            int c0 = bn0 + wn * 32 + ni * 8 + tg * 2;
            float w0 = ws[c0], w1 = ws[c0 + 1];
            float b0 = bias[c0], b1 = bias[c0 + 1];
            float2 v0, v1;
            v0.x = (float)acc[mi][ni][0] * s0 * w0 + b0;
            v0.y = (float)acc[mi][ni][1] * s0 * w1 + b1;
            v1.x = (float)acc[mi][ni][2] * s1 * w0 + b0;
            v1.y = (float)acc[mi][ni][3] * s1 * w1 + b1;
            *(float2*)&out[(size_t)r0 * D_DIM + c0]       = v0;
            *(float2*)&out[(size_t)(r0 + 8) * D_DIM + c0] = v1;
        }
    }
}

// ---------------------------------------------------------------------------
extern "C" void kernel_launch(void* const* d_in, const int* in_sizes, int n_in,
                              void* d_out, int out_size) {
    const float* x    = (const float*)d_in[0];
    const int*   w    = (const int*)d_in[1];
    const float* ws   = (const float*)d_in[2];
    const float* bias = (const float*)d_in[3];
    float* out = (float*)d_out;

    const int N = in_sizes[0] / D_DIM;   // 4096

    // 1) weight repack: 4096*4096/4 uint32 outputs
    {
        int total4 = (D_DIM * D_DIM) / 4;
        convert_w_kernel<<<(total4 + 255) / 256, 256>>>(w, total4);
    }
    // 2) Hadamard + quantize: one CTA per row
    had_quant_kernel<<<N, 256>>>(x);
    // 3) GEMM + dequant epilogue
    {
        dim3 grid(D_DIM / BN, N / BM);
        gemm_s8_kernel<<<grid, 256>>>(nullptr, ws, bias, out);
    }
}